// round 1
// baseline (speedup 1.0000x reference)
#include <cuda_runtime.h>
#include <math.h>

#define NTOK 2048
#define DIM  512
#define FDIM 512
#define NEXP 64
#define TOPK 6
#define NSH  2
#define TM   64

// ---------------- scratch (static device allocations are allowed) ----------------
__device__ int   g_topi[NTOK*TOPK];
__device__ float g_topw[NTOK*TOPK];
__device__ int   g_base[NEXP];
__device__ int   g_cnt [NEXP];
__device__ int   g_ptok[NTOK*TOPK];
__device__ float g_pw  [NTOK*TOPK];
__device__ int   g_slot[NTOK*TOPK];
__device__ float g_Yp  [NTOK*TOPK*DIM];   // routed per-(token,expert) weighted down-proj output (25 MB)
__device__ float g_Ysh [NSH*NTOK*DIM];    // shared expert outputs (8 MB)

// ---------------- 1) router: logits -> softmax -> top-6 -> renorm ----------------
__global__ void router_kernel(const float* __restrict__ x, const float* __restrict__ Wr)
{
    __shared__ float xs[DIM];
    __shared__ float l[NEXP];
    const int t = blockIdx.x;
    const int e = threadIdx.x;

    for (int i = e; i < DIM; i += NEXP) xs[i] = x[(size_t)t*DIM + i];
    __syncthreads();

    float acc = 0.f;
    #pragma unroll 8
    for (int d = 0; d < DIM; d++) acc = fmaf(xs[d], Wr[d*NEXP + e], acc);
    l[e] = acc;
    __syncthreads();

    if (e == 0) {
        float mx = -1e30f;
        for (int i = 0; i < NEXP; i++) mx = fmaxf(mx, l[i]);
        float p[NEXP];
        for (int i = 0; i < NEXP; i++) p[i] = expf(l[i] - mx);
        // top-6 by unnormalized p (softmax monotonic); renorm cancels the 1/sum
        int   bi[TOPK];
        float bw[TOPK];
        float ws = 0.f;
        for (int k = 0; k < TOPK; k++) {
            float best = -1.f; int bidx = 0;
            for (int i = 0; i < NEXP; i++) { if (p[i] > best) { best = p[i]; bidx = i; } }
            bi[k] = bidx; bw[k] = best; ws += best;
            p[bidx] = -2.f;
        }
        float inv = 1.f / ws;
        for (int k = 0; k < TOPK; k++) {
            g_topi[t*TOPK + k] = bi[k];
            g_topw[t*TOPK + k] = bw[k] * inv;
        }
    }
}

// ------------- 2) deterministic per-expert token lists (no atomics) --------------
// 256 threads: expert e = tid>>2 scans quarter p = tid&3 of the 12288 assignments.
__global__ void build_kernel()
{
    extern __shared__ int stopi[];           // 12288 ints
    __shared__ int scnt[256];
    __shared__ int sbase[256];
    const int tid = threadIdx.x;

    for (int i = tid; i < NTOK*TOPK; i += 256) stopi[i] = g_topi[i];
    __syncthreads();

    const int e  = tid >> 2;
    const int p  = tid & 3;
    const int lo = p * (NTOK*TOPK/4);
    const int hi = lo + (NTOK*TOPK/4);

    int c = 0;
    for (int i = lo; i < hi; i++) c += (stopi[i] == e);
    scnt[tid] = c;
    __syncthreads();

    if (tid == 0) {
        int s = 0;
        for (int i = 0; i < 256; i++) { sbase[i] = s; s += scnt[i]; }
    }
    __syncthreads();

    if (p == 0) {
        g_base[e] = sbase[tid];
        g_cnt[e]  = scnt[tid] + scnt[tid+1] + scnt[tid+2] + scnt[tid+3];
    }
    int pos = sbase[tid];
    for (int i = lo; i < hi; i++) {
        if (stopi[i] == e) {
            g_ptok[pos] = i / TOPK;
            g_pw[pos]   = g_topw[i];
            g_slot[i]   = pos;
            pos++;
        }
    }
}

// ---------------- 3) fused SwiGLU FFN per (expert, 64-token tile) ----------------
// Stage 1: H[f][m] = silu(X·Wg)[m][f] * (X·Wu)[m][f]  (kept in smem, f-major, pad 68)
// Stage 2: Y[m][d] = (sum_f H[f][m]*Wd[f][d]) * w[m]  -> global scratch slot rows
#define XS_LD 68
#define HS_LD 68
#define FFN_SMEM_FLOATS (512*HS_LD + 32*XS_LD + 32*128 + 32*128 + 128)
#define FFN_SMEM_BYTES  (FFN_SMEM_FLOATS*4)

template<bool SH>
__global__ void __launch_bounds__(256, 1) ffn_kernel(
    const float* __restrict__ X,
    const float* __restrict__ Wgp,
    const float* __restrict__ Wup,
    const float* __restrict__ Wdp)
{
    extern __shared__ float sm[];
    float* Hs  = sm;                        // 512*68
    float* Xs  = Hs + 512*HS_LD;            // 32*68
    float* B0  = Xs + 32*XS_LD;             // 32*128
    float* B1  = B0 + 32*128;               // 32*128
    int*   tok = (int*)(B1 + 32*128);       // 64
    float* wro = (float*)(tok + 64);        // 64

    const int e    = blockIdx.y;
    const int tile = blockIdx.x;
    const int tid  = threadIdx.x;
    const int cntE = SH ? NTOK : g_cnt[e];
    const int m0   = tile * TM;
    if (m0 >= cntE) return;
    const int baseE = SH ? e*NTOK : g_base[e];
    const int M     = min(TM, cntE - m0);
    float* Yout     = SH ? g_Ysh : g_Yp;

    if (tid < TM) {
        if (tid < M) {
            tok[tid] = SH ? (m0 + tid) : g_ptok[baseE + m0 + tid];
            wro[tid] = SH ? 1.f        : g_pw  [baseE + m0 + tid];
        } else { tok[tid] = 0; wro[tid] = 0.f; }
    }
    __syncthreads();

    const float* Wge = Wgp + (size_t)e*DIM*FDIM;
    const float* Wue = Wup + (size_t)e*DIM*FDIM;
    const float* Wde = Wdp + (size_t)e*FDIM*DIM;

    // ---------------- stage 1 ----------------
    {
        const int ty = tid >> 5, tx = tid & 31;
        const int msub = ty * 8, nsub = tx * 4;      // 8x4 microtile, n-chunk 128
        for (int nc = 0; nc < FDIM; nc += 128) {
            float ag[8][4], au[8][4];
            #pragma unroll
            for (int i = 0; i < 8; i++)
                #pragma unroll
                for (int j = 0; j < 4; j++) { ag[i][j] = 0.f; au[i][j] = 0.f; }

            for (int kc = 0; kc < DIM; kc += 32) {
                // gather X tile (64 rows x 32 k), transposed into Xs[kk][m]
                #pragma unroll
                for (int r = 0; r < 2; r++) {
                    int i4 = tid + 256*r;
                    int m = i4 >> 3, f4 = i4 & 7;
                    float4 v = *(const float4*)(X + (size_t)tok[m]*DIM + kc + f4*4);
                    Xs[(f4*4+0)*XS_LD + m] = v.x;
                    Xs[(f4*4+1)*XS_LD + m] = v.y;
                    Xs[(f4*4+2)*XS_LD + m] = v.z;
                    Xs[(f4*4+3)*XS_LD + m] = v.w;
                }
                // Wg/Wu chunks (32 x 128)
                #pragma unroll
                for (int r = 0; r < 4; r++) {
                    int i4 = tid + 256*r;
                    int kk = i4 >> 5, n4 = i4 & 31;
                    *(float4*)(B0 + kk*128 + n4*4) =
                        *(const float4*)(Wge + (size_t)(kc+kk)*FDIM + nc + n4*4);
                    *(float4*)(B1 + kk*128 + n4*4) =
                        *(const float4*)(Wue + (size_t)(kc+kk)*FDIM + nc + n4*4);
                }
                __syncthreads();
                #pragma unroll
                for (int kk = 0; kk < 32; kk++) {
                    float4 a0 = *(const float4*)(Xs + kk*XS_LD + msub);
                    float4 a1 = *(const float4*)(Xs + kk*XS_LD + msub + 4);
                    float4 bg = *(const float4*)(B0 + kk*128 + nsub);
                    float4 bu = *(const float4*)(B1 + kk*128 + nsub);
                    float a[8]  = {a0.x,a0.y,a0.z,a0.w,a1.x,a1.y,a1.z,a1.w};
                    float bgv[4]= {bg.x,bg.y,bg.z,bg.w};
                    float buv[4]= {bu.x,bu.y,bu.z,bu.w};
                    #pragma unroll
                    for (int i = 0; i < 8; i++)
                        #pragma unroll
                        for (int j = 0; j < 4; j++) {
                            ag[i][j] = fmaf(a[i], bgv[j], ag[i][j]);
                            au[i][j] = fmaf(a[i], buv[j], au[i][j]);
                        }
                }
                __syncthreads();
            }
            // silu(g)*u -> Hs (f-major)
            #pragma unroll
            for (int i = 0; i < 8; i++)
                #pragma unroll
                for (int j = 0; j < 4; j++) {
                    float g = ag[i][j];
                    float s = 1.f / (1.f + __expf(-g));
                    Hs[(nc + nsub + j)*HS_LD + msub + i] = g * s * au[i][j];
                }
            __syncthreads();
        }
    }
    __syncthreads();

    // ---------------- stage 2 ----------------
    {
        const int ty = tid >> 4, tx = tid & 15;
        const int msub = ty * 4, nsub = tx * 4;      // 4x4 microtile, n-chunk 64
        for (int nc = 0; nc < DIM; nc += 64) {
            float ac[4][4];
            #pragma unroll
            for (int i = 0; i < 4; i++)
                #pragma unroll
                for (int j = 0; j < 4; j++) ac[i][j] = 0.f;

            for (int kc = 0; kc < FDIM; kc += 32) {
                #pragma unroll
                for (int r = 0; r < 2; r++) {
                    int i4 = tid + 256*r;
                    int kk = i4 >> 4, n4 = i4 & 15;
                    *(float4*)(B0 + kk*64 + n4*4) =
                        *(const float4*)(Wde + (size_t)(kc+kk)*DIM + nc + n4*4);
                }
                __syncthreads();
                #pragma unroll
                for (int kk = 0; kk < 32; kk++) {
                    float4 a4 = *(const float4*)(Hs + (size_t)(kc+kk)*HS_LD + msub);
                    float4 b4 = *(const float4*)(B0 + kk*64 + nsub);
                    float a[4] = {a4.x,a4.y,a4.z,a4.w};
                    float b[4] = {b4.x,b4.y,b4.z,b4.w};
                    #pragma unroll
                    for (int i = 0; i < 4; i++)
                        #pragma unroll
                        for (int j = 0; j < 4; j++)
                            ac[i][j] = fmaf(a[i], b[j], ac[i][j]);
                }
                __syncthreads();
            }
            #pragma unroll
            for (int i = 0; i < 4; i++) {
                int m = msub + i;
                if (m < M) {
                    float w = wro[m];
                    float4 o = make_float4(ac[i][0]*w, ac[i][1]*w, ac[i][2]*w, ac[i][3]*w);
                    *(float4*)(Yout + (size_t)(baseE + m0 + m)*DIM + nc + nsub) = o;
                }
            }
        }
    }
}

// ---------------- 4) combine: out = x + shared0 + shared1 + sum_k routed ----------
__global__ void combine_kernel(const float* __restrict__ x, float* __restrict__ out)
{
    __shared__ int sl[TOPK];
    const int b = blockIdx.x;
    const int t = b >> 1;
    const int d = ((b & 1) << 8) + threadIdx.x;
    if (threadIdx.x < TOPK) sl[threadIdx.x] = g_slot[t*TOPK + threadIdx.x];
    __syncthreads();

    const size_t o = (size_t)t*DIM + d;
    float v = x[o] + g_Ysh[o] + g_Ysh[(size_t)NTOK*DIM + o];
    #pragma unroll
    for (int k = 0; k < TOPK; k++) v += g_Yp[(size_t)sl[k]*DIM + d];
    out[o] = v;
}

// ---------------------------------- launch ---------------------------------------
extern "C" void kernel_launch(void* const* d_in, const int* in_sizes, int n_in,
                              void* d_out, int out_size)
{
    const float* x   = (const float*)d_in[0];
    const float* Wr  = (const float*)d_in[1];
    const float* sWg = (const float*)d_in[2];
    const float* sWu = (const float*)d_in[3];
    const float* sWd = (const float*)d_in[4];
    const float* Wg  = (const float*)d_in[5];
    const float* Wu  = (const float*)d_in[6];
    const float* Wd  = (const float*)d_in[7];
    float* out = (float*)d_out;

    cudaFuncSetAttribute(ffn_kernel<true>,  cudaFuncAttributeMaxDynamicSharedMemorySize, FFN_SMEM_BYTES);
    cudaFuncSetAttribute(ffn_kernel<false>, cudaFuncAttributeMaxDynamicSharedMemorySize, FFN_SMEM_BYTES);
    cudaFuncSetAttribute(build_kernel, cudaFuncAttributeMaxDynamicSharedMemorySize, NTOK*TOPK*4);

    router_kernel<<<NTOK, NEXP>>>(x, Wr);
    build_kernel<<<1, 256, NTOK*TOPK*4>>>();
    ffn_kernel<true ><<<dim3(NTOK/TM, NSH ), 256, FFN_SMEM_BYTES>>>(x, sWg, sWu, sWd);
    ffn_kernel<false><<<dim3(NTOK/TM, NEXP), 256, FFN_SMEM_BYTES>>>(x, Wg,  Wu,  Wd);
    combine_kernel<<<NTOK*2, 256>>>(x, out);
}

// round 4
// speedup vs baseline: 2.0361x; 2.0361x over previous
#include <cuda_runtime.h>
#include <cuda_bf16.h>
#include <math.h>
#include <stdint.h>

#define NTOK 2048
#define DIM  512
#define FDIM 512
#define NEXP 64
#define TOPK 6
#define NSH  2
#define MT   128

// smem layout (bytes). ldmatrix needs 16B-aligned rows; strides chosen bank-conflict-free:
//  H rows: 1040B (65*16)  -> (4r)%32 distinct across 8 rows
//  X/B rows: 144B (9*16)  -> (4r)%32 distinct across 8 rows
#define H_STRIDE 1040
#define T_STRIDE 144
#define SM_H   0                       // 128*1040 = 133120
#define SM_X   133120                  // 128*144  = 18432
#define SM_B0  151552                  // 64*144   = 9216
#define SM_B1  160768                  // 64*144   = 9216
#define SM_TOK 169984                  // 128*4
#define SM_WRO 170496                  // 128*4
#define SMEM_BYTES 171008

// ---------------- scratch ----------------
__device__ int   g_topi[NTOK*TOPK];
__device__ float g_topw[NTOK*TOPK];
__device__ int   g_base[NEXP];
__device__ int   g_cnt [NEXP];
__device__ int   g_ptok[NTOK*TOPK];
__device__ float g_pw  [NTOK*TOPK];
__device__ int   g_slot[NTOK*TOPK];
__device__ float g_Yp  [NTOK*TOPK*DIM];
__device__ float g_Ysh [NSH*NTOK*DIM];

// ---------------- helpers ----------------
__device__ __forceinline__ uint32_t smem_u32(const void* p) {
    uint32_t a;
    asm("{ .reg .u64 t; cvta.to.shared.u64 t, %1; cvt.u32.u64 %0, t; }" : "=r"(a) : "l"(p));
    return a;
}
__device__ __forceinline__ uint32_t pack_bf16x2(float lo, float hi) {
    uint32_t r;
    asm("cvt.rn.satfinite.bf16x2.f32 %0, %1, %2;" : "=r"(r) : "f"(hi), "f"(lo));
    return r;
}
__device__ __forceinline__ void ldmx4(uint32_t* r, uint32_t a) {
    asm volatile("ldmatrix.sync.aligned.m8n8.x4.shared.b16 {%0,%1,%2,%3}, [%4];"
        : "=r"(r[0]), "=r"(r[1]), "=r"(r[2]), "=r"(r[3]) : "r"(a));
}
__device__ __forceinline__ void ldmx2(uint32_t* r, uint32_t a) {
    asm volatile("ldmatrix.sync.aligned.m8n8.x2.shared.b16 {%0,%1}, [%2];"
        : "=r"(r[0]), "=r"(r[1]) : "r"(a));
}
__device__ __forceinline__ void mma16816(float* d, const uint32_t* a, const uint32_t* b) {
    asm volatile("mma.sync.aligned.m16n8k16.row.col.f32.bf16.bf16.f32 "
        "{%0,%1,%2,%3}, {%4,%5,%6,%7}, {%8,%9}, {%0,%1,%2,%3};"
        : "+f"(d[0]), "+f"(d[1]), "+f"(d[2]), "+f"(d[3])
        : "r"(a[0]), "r"(a[1]), "r"(a[2]), "r"(a[3]), "r"(b[0]), "r"(b[1]));
}

// ---------------- 1) router ----------------
__global__ void router_kernel(const float* __restrict__ x, const float* __restrict__ Wr)
{
    __shared__ float xs[DIM];
    __shared__ float l[NEXP];
    const int t = blockIdx.x;
    const int e = threadIdx.x;

    for (int i = e; i < DIM; i += NEXP) xs[i] = x[(size_t)t*DIM + i];
    __syncthreads();

    float acc = 0.f;
    #pragma unroll 8
    for (int d = 0; d < DIM; d++) acc = fmaf(xs[d], Wr[d*NEXP + e], acc);
    l[e] = acc;
    __syncthreads();

    if (e == 0) {
        float mx = -1e30f;
        for (int i = 0; i < NEXP; i++) mx = fmaxf(mx, l[i]);
        float p[NEXP];
        for (int i = 0; i < NEXP; i++) p[i] = expf(l[i] - mx);
        int bi[TOPK]; float bw[TOPK]; float ws = 0.f;
        for (int k = 0; k < TOPK; k++) {
            float best = -1.f; int bidx = 0;
            for (int i = 0; i < NEXP; i++) if (p[i] > best) { best = p[i]; bidx = i; }
            bi[k] = bidx; bw[k] = best; ws += best;
            p[bidx] = -2.f;
        }
        float inv = 1.f / ws;
        for (int k = 0; k < TOPK; k++) {
            g_topi[t*TOPK + k] = bi[k];
            g_topw[t*TOPK + k] = bw[k] * inv;
        }
    }
}

// ---------------- 2) deterministic per-expert lists ----------------
__global__ void build_kernel()
{
    extern __shared__ int stopi[];
    __shared__ int scnt[256];
    __shared__ int sbase[256];
    const int tid = threadIdx.x;

    for (int i = tid; i < NTOK*TOPK; i += 256) stopi[i] = g_topi[i];
    __syncthreads();

    const int e  = tid >> 2;
    const int p  = tid & 3;
    const int lo = p * (NTOK*TOPK/4);
    const int hi = lo + (NTOK*TOPK/4);

    int c = 0;
    for (int i = lo; i < hi; i++) c += (stopi[i] == e);
    scnt[tid] = c;
    __syncthreads();

    if (tid == 0) {
        int s = 0;
        for (int i = 0; i < 256; i++) { sbase[i] = s; s += scnt[i]; }
    }
    __syncthreads();

    if (p == 0) {
        g_base[e] = sbase[tid];
        g_cnt[e]  = scnt[tid] + scnt[tid+1] + scnt[tid+2] + scnt[tid+3];
    }
    int pos = sbase[tid];
    for (int i = lo; i < hi; i++) {
        if (stopi[i] == e) {
            g_ptok[pos] = i / TOPK;
            g_pw[pos]   = g_topw[i];
            g_slot[i]   = pos;
            pos++;
        }
    }
}

// ---------------- 3) mma.sync bf16 fused SwiGLU FFN ----------------
// per CTA: expert e, 128-token tile. 8 warps in 4(m) x 2(n) grid.
// stage 1: H[128,512] = silu(X*Wg) .* (X*Wu)   (H bf16 in smem)
// stage 2: Y[128,512] = (H*Wd) * w             (to global scratch)
template<bool SH>
__global__ void __launch_bounds__(256, 1) moe_ffn(
    const float* __restrict__ X,
    const float* __restrict__ Wgp,
    const float* __restrict__ Wup,
    const float* __restrict__ Wdp)
{
    extern __shared__ char smem[];
    const int tid = threadIdx.x, wid = tid >> 5, lane = tid & 31;
    const int e = blockIdx.y, tile = blockIdx.x;
    const int cnt = SH ? NTOK : g_cnt[e];
    const int m0  = tile * MT;
    if (m0 >= cnt) return;
    const int base = SH ? e*NTOK : g_base[e];
    const int M    = min(MT, cnt - m0);
    float* Yout    = SH ? g_Ysh : g_Yp;

    int*   tok = (int*)(smem + SM_TOK);
    float* wro = (float*)(smem + SM_WRO);
    const uint32_t sb = smem_u32(smem);

    if (tid < MT) {
        if (tid < M) {
            tok[tid] = SH ? (m0 + tid) : g_ptok[base + m0 + tid];
            wro[tid] = SH ? 1.f        : g_pw  [base + m0 + tid];
        } else { tok[tid] = 0; wro[tid] = 0.f; }
    }
    __syncthreads();

    const float* Wge = Wgp + (size_t)e*DIM*FDIM;
    const float* Wue = Wup + (size_t)e*DIM*FDIM;
    const float* Wde = Wdp + (size_t)e*FDIM*DIM;

    const int mw = wid >> 1;            // 0..3 -> m base mw*32
    const int nw = wid & 1;             // 0..1 -> n base nw*32
    const int quad = lane >> 2;         // fragment row 0..7
    const int tq   = lane & 3;          // fragment col pair

    // ================= stage 1 =================
    for (int nc = 0; nc < FDIM; nc += 64) {
        float ag[2][4][4], au[2][4][4];
        #pragma unroll
        for (int i = 0; i < 2; i++)
            #pragma unroll
            for (int j = 0; j < 4; j++)
                #pragma unroll
                for (int q = 0; q < 4; q++) { ag[i][j][q] = 0.f; au[i][j][q] = 0.f; }

        for (int kc = 0; kc < DIM; kc += 64) {
            // --- X tile [128m x 64k] bf16 (row-major k-contig, stride 144) ---
            #pragma unroll
            for (int it = 0; it < 4; it++) {
                int t = tid + it*256;
                int m = t >> 3, q = t & 7;
                const float* s = X + (size_t)tok[m]*DIM + kc + q*8;
                float4 a = *(const float4*)s, b = *(const float4*)(s + 4);
                *(uint4*)(smem + SM_X + m*T_STRIDE + q*16) = make_uint4(
                    pack_bf16x2(a.x, a.y), pack_bf16x2(a.z, a.w),
                    pack_bf16x2(b.x, b.y), pack_bf16x2(b.z, b.w));
            }
            // --- Wg/Wu tiles [64n x 64k] bf16 transposed-on-load ---
            #pragma unroll
            for (int it = 0; it < 2; it++) {
                int t = tid + it*256;
                int n = t & 63, kg = t >> 6;
                const float* sg = Wge + (size_t)(kc + kg*8)*FDIM + nc + n;
                const float* su = Wue + (size_t)(kc + kg*8)*FDIM + nc + n;
                float vg[8], vu[8];
                #pragma unroll
                for (int j = 0; j < 8; j++) { vg[j] = sg[(size_t)j*FDIM]; vu[j] = su[(size_t)j*FDIM]; }
                *(uint4*)(smem + SM_B0 + n*T_STRIDE + kg*16) = make_uint4(
                    pack_bf16x2(vg[0],vg[1]), pack_bf16x2(vg[2],vg[3]),
                    pack_bf16x2(vg[4],vg[5]), pack_bf16x2(vg[6],vg[7]));
                *(uint4*)(smem + SM_B1 + n*T_STRIDE + kg*16) = make_uint4(
                    pack_bf16x2(vu[0],vu[1]), pack_bf16x2(vu[2],vu[3]),
                    pack_bf16x2(vu[4],vu[5]), pack_bf16x2(vu[6],vu[7]));
            }
            __syncthreads();
            // --- mma: warp tile 32m x 32n, k=64 in 4 steps of 16 ---
            #pragma unroll
            for (int ks = 0; ks < 4; ks++) {
                uint32_t afr[2][4];
                #pragma unroll
                for (int ms = 0; ms < 2; ms++)
                    ldmx4(afr[ms], sb + SM_X + (mw*32 + ms*16 + (lane & 15))*T_STRIDE
                                      + (ks*16 + (lane >> 4)*8)*2);
                #pragma unroll
                for (int j = 0; j < 4; j++) {
                    uint32_t bg[2], bu[2];
                    uint32_t boff = (nw*32 + j*8 + (lane & 7))*T_STRIDE
                                  + (ks*16 + ((lane >> 3) & 1)*8)*2;
                    ldmx2(bg, sb + SM_B0 + boff);
                    ldmx2(bu, sb + SM_B1 + boff);
                    #pragma unroll
                    for (int ms = 0; ms < 2; ms++) {
                        mma16816(ag[ms][j], afr[ms], bg);
                        mma16816(au[ms][j], afr[ms], bu);
                    }
                }
            }
            __syncthreads();
        }
        // --- epilogue: silu(g)*u -> H bf16 ---
        #pragma unroll
        for (int ms = 0; ms < 2; ms++)
            #pragma unroll
            for (int j = 0; j < 4; j++)
                #pragma unroll
                for (int half = 0; half < 2; half++) {
                    int m   = mw*32 + ms*16 + quad + half*8;
                    int col = nc + nw*32 + j*8 + tq*2;
                    float g0 = ag[ms][j][half*2+0], g1 = ag[ms][j][half*2+1];
                    float u0 = au[ms][j][half*2+0], u1 = au[ms][j][half*2+1];
                    float h0 = g0 * u0 * __frcp_rn(1.f + __expf(-g0));
                    float h1 = g1 * u1 * __frcp_rn(1.f + __expf(-g1));
                    *(uint32_t*)(smem + SM_H + m*H_STRIDE + col*2) = pack_bf16x2(h0, h1);
                }
    }
    __syncthreads();

    // ================= stage 2 =================
    for (int nc2 = 0; nc2 < DIM; nc2 += 64) {
        float ac[2][4][4];
        #pragma unroll
        for (int i = 0; i < 2; i++)
            #pragma unroll
            for (int j = 0; j < 4; j++)
                #pragma unroll
                for (int q = 0; q < 4; q++) ac[i][j][q] = 0.f;

        for (int kc = 0; kc < FDIM; kc += 64) {
            #pragma unroll
            for (int it = 0; it < 2; it++) {
                int t = tid + it*256;
                int n = t & 63, kg = t >> 6;
                const float* sd = Wde + (size_t)(kc + kg*8)*DIM + nc2 + n;
                float v[8];
                #pragma unroll
                for (int j = 0; j < 8; j++) v[j] = sd[(size_t)j*DIM];
                *(uint4*)(smem + SM_B0 + n*T_STRIDE + kg*16) = make_uint4(
                    pack_bf16x2(v[0],v[1]), pack_bf16x2(v[2],v[3]),
                    pack_bf16x2(v[4],v[5]), pack_bf16x2(v[6],v[7]));
            }
            __syncthreads();
            #pragma unroll
            for (int ks = 0; ks < 4; ks++) {
                uint32_t afr[2][4];
                #pragma unroll
                for (int ms = 0; ms < 2; ms++)
                    ldmx4(afr[ms], sb + SM_H + (mw*32 + ms*16 + (lane & 15))*H_STRIDE
                                      + (kc + ks*16 + (lane >> 4)*8)*2);
                #pragma unroll
                for (int j = 0; j < 4; j++) {
                    uint32_t bd[2];
                    ldmx2(bd, sb + SM_B0 + (nw*32 + j*8 + (lane & 7))*T_STRIDE
                                 + (ks*16 + ((lane >> 3) & 1)*8)*2);
                    #pragma unroll
                    for (int ms = 0; ms < 2; ms++)
                        mma16816(ac[ms][j], afr[ms], bd);
                }
            }
            __syncthreads();
        }
        // --- epilogue: scale by routing weight, store fp32 ---
        #pragma unroll
        for (int ms = 0; ms < 2; ms++)
            #pragma unroll
            for (int half = 0; half < 2; half++) {
                int m = mw*32 + ms*16 + quad + half*8;
                if (m < M) {
                    float w = wro[m];
                    float* dst = Yout + (size_t)(base + m0 + m)*DIM + nc2;
                    #pragma unroll
                    for (int j = 0; j < 4; j++) {
                        int col = nw*32 + j*8 + tq*2;
                        float2 o = make_float2(ac[ms][j][half*2+0]*w, ac[ms][j][half*2+1]*w);
                        *(float2*)(dst + col) = o;
                    }
                }
            }
    }
}

// ---------------- 4) combine ----------------
__global__ void combine_kernel(const float* __restrict__ x, float* __restrict__ out)
{
    __shared__ int sl[TOPK];
    const int b = blockIdx.x;
    const int t = b >> 1;
    const int d = ((b & 1) << 8) + threadIdx.x;
    if (threadIdx.x < TOPK) sl[threadIdx.x] = g_slot[t*TOPK + threadIdx.x];
    __syncthreads();

    const size_t o = (size_t)t*DIM + d;
    float v = x[o] + g_Ysh[o] + g_Ysh[(size_t)NTOK*DIM + o];
    #pragma unroll
    for (int k = 0; k < TOPK; k++) v += g_Yp[(size_t)sl[k]*DIM + d];
    out[o] = v;
}

// ---------------------------------- launch ---------------------------------------
extern "C" void kernel_launch(void* const* d_in, const int* in_sizes, int n_in,
                              void* d_out, int out_size)
{
    const float* x   = (const float*)d_in[0];
    const float* Wr  = (const float*)d_in[1];
    const float* sWg = (const float*)d_in[2];
    const float* sWu = (const float*)d_in[3];
    const float* sWd = (const float*)d_in[4];
    const float* Wg  = (const float*)d_in[5];
    const float* Wu  = (const float*)d_in[6];
    const float* Wd  = (const float*)d_in[7];
    float* out = (float*)d_out;

    cudaFuncSetAttribute(moe_ffn<true>,  cudaFuncAttributeMaxDynamicSharedMemorySize, SMEM_BYTES);
    cudaFuncSetAttribute(moe_ffn<false>, cudaFuncAttributeMaxDynamicSharedMemorySize, SMEM_BYTES);
    cudaFuncSetAttribute(build_kernel,   cudaFuncAttributeMaxDynamicSharedMemorySize, NTOK*TOPK*4);

    router_kernel<<<NTOK, NEXP>>>(x, Wr);
    build_kernel<<<1, 256, NTOK*TOPK*4>>>();
    moe_ffn<true ><<<dim3(NTOK/MT, NSH ), 256, SMEM_BYTES>>>(x, sWg, sWu, sWd);
    moe_ffn<false><<<dim3(NTOK/MT, NEXP), 256, SMEM_BYTES>>>(x, Wg,  Wu,  Wd);
    combine_kernel<<<NTOK*2, 256>>>(x, out);
}

// round 6
// speedup vs baseline: 2.3941x; 1.1758x over previous
#include <cuda_runtime.h>
#include <cuda_bf16.h>
#include <math.h>
#include <stdint.h>

#define NTOK 2048
#define DIM  512
#define FDIM 512
#define NEXP 64
#define TOPK 6
#define NSH  2
#define MT   128

// smem layout (bytes); strides bank-conflict-free for ldmatrix (step 4 banks/row)
#define H_STRIDE 1040
#define T_STRIDE 144
#define XBUF 18432                     // 128*144
#define BBUF 9216                      // 64*144
#define SM_H   0                       // 128*1040 = 133120
#define SM_X   133120                  // 2*XBUF   = 36864
#define SM_B0  169984                  // 2*BBUF   = 18432
#define SM_B1  188416                  // 2*BBUF   = 18432
#define SM_TOK 206848                  // 128*4
#define SM_WRO 207360                  // 128*4
#define SMEM_BYTES 207872

// ---------------- scratch ----------------
__device__ int   g_topi[NTOK*TOPK];
__device__ float g_topw[NTOK*TOPK];
__device__ int   g_base[NEXP];
__device__ int   g_cnt [NEXP];
__device__ int   g_ptok[NTOK*TOPK];
__device__ float g_pw  [NTOK*TOPK];
__device__ int   g_slot[NTOK*TOPK];
__device__ float g_Yp  [NTOK*TOPK*DIM];
__device__ float g_Ysh [NSH*NTOK*DIM];

// ---------------- helpers ----------------
__device__ __forceinline__ uint32_t smem_u32(const void* p) {
    uint32_t a;
    asm("{ .reg .u64 t; cvta.to.shared.u64 t, %1; cvt.u32.u64 %0, t; }" : "=r"(a) : "l"(p));
    return a;
}
__device__ __forceinline__ uint32_t pack_bf16x2(float lo, float hi) {
    uint32_t r;
    asm("cvt.rn.satfinite.bf16x2.f32 %0, %1, %2;" : "=r"(r) : "f"(hi), "f"(lo));
    return r;
}
__device__ __forceinline__ void ldmx4(uint32_t* r, uint32_t a) {
    asm volatile("ldmatrix.sync.aligned.m8n8.x4.shared.b16 {%0,%1,%2,%3}, [%4];"
        : "=r"(r[0]), "=r"(r[1]), "=r"(r[2]), "=r"(r[3]) : "r"(a));
}
__device__ __forceinline__ void ldmx2(uint32_t* r, uint32_t a) {
    asm volatile("ldmatrix.sync.aligned.m8n8.x2.shared.b16 {%0,%1}, [%2];"
        : "=r"(r[0]), "=r"(r[1]) : "r"(a));
}
__device__ __forceinline__ void mma16816(float* d, const uint32_t* a, const uint32_t* b) {
    asm volatile("mma.sync.aligned.m16n8k16.row.col.f32.bf16.bf16.f32 "
        "{%0,%1,%2,%3}, {%4,%5,%6,%7}, {%8,%9}, {%0,%1,%2,%3};"
        : "+f"(d[0]), "+f"(d[1]), "+f"(d[2]), "+f"(d[3])
        : "r"(a[0]), "r"(a[1]), "r"(a[2]), "r"(a[3]), "r"(b[0]), "r"(b[1]));
}
__device__ __forceinline__ uint4 pack8(float4 a, float4 b) {
    return make_uint4(pack_bf16x2(a.x, a.y), pack_bf16x2(a.z, a.w),
                      pack_bf16x2(b.x, b.y), pack_bf16x2(b.z, b.w));
}

// ---------------- 1) router ----------------
__global__ void router_kernel(const float* __restrict__ x, const float* __restrict__ Wr)
{
    __shared__ float xs[DIM];
    __shared__ float l[NEXP];
    const int t = blockIdx.x;
    const int e = threadIdx.x;

    for (int i = e; i < DIM; i += NEXP) xs[i] = x[(size_t)t*DIM + i];
    __syncthreads();

    float acc = 0.f;
    #pragma unroll 8
    for (int d = 0; d < DIM; d++) acc = fmaf(xs[d], Wr[d*NEXP + e], acc);
    l[e] = acc;
    __syncthreads();

    if (e == 0) {
        float mx = -1e30f;
        for (int i = 0; i < NEXP; i++) mx = fmaxf(mx, l[i]);
        float p[NEXP];
        for (int i = 0; i < NEXP; i++) p[i] = expf(l[i] - mx);
        int bi[TOPK]; float bw[TOPK]; float ws = 0.f;
        for (int k = 0; k < TOPK; k++) {
            float best = -1.f; int bidx = 0;
            for (int i = 0; i < NEXP; i++) if (p[i] > best) { best = p[i]; bidx = i; }
            bi[k] = bidx; bw[k] = best; ws += best;
            p[bidx] = -2.f;
        }
        float inv = 1.f / ws;
        for (int k = 0; k < TOPK; k++) {
            g_topi[t*TOPK + k] = bi[k];
            g_topw[t*TOPK + k] = bw[k] * inv;
        }
    }
}

// ---------------- 2) deterministic per-expert lists ----------------
__global__ void build_kernel()
{
    extern __shared__ int stopi[];
    __shared__ int scnt[256];
    __shared__ int sbase[256];
    const int tid = threadIdx.x;

    for (int i = tid; i < NTOK*TOPK; i += 256) stopi[i] = g_topi[i];
    __syncthreads();

    const int e  = tid >> 2;
    const int p  = tid & 3;
    const int lo = p * (NTOK*TOPK/4);
    const int hi = lo + (NTOK*TOPK/4);

    int c = 0;
    for (int i = lo; i < hi; i++) c += (stopi[i] == e);
    scnt[tid] = c;
    __syncthreads();

    if (tid == 0) {
        int s = 0;
        for (int i = 0; i < 256; i++) { sbase[i] = s; s += scnt[i]; }
    }
    __syncthreads();

    if (p == 0) {
        g_base[e] = sbase[tid];
        g_cnt[e]  = scnt[tid] + scnt[tid+1] + scnt[tid+2] + scnt[tid+3];
    }
    int pos = sbase[tid];
    for (int i = lo; i < hi; i++) {
        if (stopi[i] == e) {
            g_ptok[pos] = i / TOPK;
            g_pw[pos]   = g_topw[i];
            g_slot[i]   = pos;
            pos++;
        }
    }
}

// ---------------- 3) fused routed+shared SwiGLU FFN ----------------
// 512 threads, 16 warps in 4(m) x 4(n); warp tile 32m x 16n; N-chunk 64, K-chunk 64.
// Double-buffered X/W tiles; register-staged prefetch overlaps LDG with MMA.
__global__ void __launch_bounds__(512, 1) moe_ffn(
    const float* __restrict__ X,
    const float* __restrict__ Wgp, const float* __restrict__ Wup, const float* __restrict__ Wdp,
    const float* __restrict__ sWg, const float* __restrict__ sWu, const float* __restrict__ sWd)
{
    extern __shared__ char smem[];
    const int tid = threadIdx.x, wid = tid >> 5, lane = tid & 31;
    const int ey = blockIdx.y, tile = blockIdx.x;
    const bool sh = (ey >= NEXP);
    const int e   = sh ? (ey - NEXP) : ey;
    const int cnt = sh ? NTOK : g_cnt[e];
    const int m0  = tile * MT;
    if (m0 >= cnt) return;
    const int base = sh ? e*NTOK : g_base[e];
    const int M    = min(MT, cnt - m0);
    float* Yout    = sh ? g_Ysh : g_Yp;

    const float* Wge = (sh ? sWg : Wgp) + (size_t)e*DIM*FDIM;
    const float* Wue = (sh ? sWu : Wup) + (size_t)e*DIM*FDIM;
    const float* Wde = (sh ? sWd : Wdp) + (size_t)e*FDIM*DIM;

    int*   tok = (int*)(smem + SM_TOK);
    float* wro = (float*)(smem + SM_WRO);
    const uint32_t sb = smem_u32(smem);

    if (tid < MT) {
        if (tid < M) {
            tok[tid] = sh ? (m0 + tid) : g_ptok[base + m0 + tid];
            wro[tid] = sh ? 1.f        : g_pw  [base + m0 + tid];
        } else { tok[tid] = 0; wro[tid] = 0.f; }
    }
    __syncthreads();

    // load-task geometry (fixed per thread)
    const int xm = tid >> 3, xq = tid & 7;              // X: rows xm, xm+64; 8 floats at col xq*8
    const int wn = tid & 63, wkg = tid >> 6;            // W: col n=wn, rows wkg*8..+7
    const float* xrow0 = X + (size_t)tok[xm]*DIM      + xq*8;
    const float* xrow1 = X + (size_t)tok[xm + 64]*DIM + xq*8;
    const uint32_t xsts0 = xm*T_STRIDE + xq*16;
    const uint32_t xsts1 = (xm + 64)*T_STRIDE + xq*16;
    const uint32_t wsts  = wn*T_STRIDE + wkg*16;

    // warp/fragment geometry
    const int mw = wid & 3, nw = wid >> 2;
    const int quad = lane >> 2, tq = lane & 3;
    const uint32_t arow = (mw*32 + (lane & 15))*T_STRIDE + (lane >> 4)*8*2;
    const uint32_t hrow = (mw*32 + (lane & 15))*H_STRIDE + (lane >> 4)*8*2;
    const uint32_t brow = (nw*16 + (lane & 7))*T_STRIDE + ((lane >> 3) & 1)*8*2;

    // ================= stage 1: H = silu(X*Wg) .* (X*Wu) =================
    for (int nc = 0; nc < FDIM; nc += 64) {
        float ag[2][2][4], au[2][2][4];
        #pragma unroll
        for (int i = 0; i < 2; i++)
            #pragma unroll
            for (int j = 0; j < 2; j++)
                #pragma unroll
                for (int q = 0; q < 4; q++) { ag[i][j][q] = 0.f; au[i][j][q] = 0.f; }

        const float* wgb = Wge + (size_t)wkg*8*FDIM + nc + wn;
        const float* wub = Wue + (size_t)wkg*8*FDIM + nc + wn;

        // prologue: chunk 0 -> buffer 0
        {
            float4 a0 = *(const float4*)(xrow0), b0 = *(const float4*)(xrow0 + 4);
            float4 a1 = *(const float4*)(xrow1), b1 = *(const float4*)(xrow1 + 4);
            float vg[8], vu[8];
            #pragma unroll
            for (int j = 0; j < 8; j++) { vg[j] = wgb[(size_t)j*FDIM]; vu[j] = wub[(size_t)j*FDIM]; }
            *(uint4*)(smem + SM_X + xsts0) = pack8(a0, b0);
            *(uint4*)(smem + SM_X + xsts1) = pack8(a1, b1);
            *(uint4*)(smem + SM_B0 + wsts) = make_uint4(
                pack_bf16x2(vg[0],vg[1]), pack_bf16x2(vg[2],vg[3]),
                pack_bf16x2(vg[4],vg[5]), pack_bf16x2(vg[6],vg[7]));
            *(uint4*)(smem + SM_B1 + wsts) = make_uint4(
                pack_bf16x2(vu[0],vu[1]), pack_bf16x2(vu[2],vu[3]),
                pack_bf16x2(vu[4],vu[5]), pack_bf16x2(vu[6],vu[7]));
        }
        __syncthreads();

        for (int kci = 0; kci < 8; kci++) {
            const int cur = kci & 1;
            const bool more = (kci < 7);
            // prefetch next chunk into registers (overlaps with mma below)
            float4 pa0, pb0, pa1, pb1; float vg[8], vu[8];
            if (more) {
                const int kc = (kci + 1)*64;
                pa0 = *(const float4*)(xrow0 + kc); pb0 = *(const float4*)(xrow0 + kc + 4);
                pa1 = *(const float4*)(xrow1 + kc); pb1 = *(const float4*)(xrow1 + kc + 4);
                const float* g = wgb + (size_t)kc*FDIM;
                const float* u = wub + (size_t)kc*FDIM;
                #pragma unroll
                for (int j = 0; j < 8; j++) { vg[j] = g[(size_t)j*FDIM]; vu[j] = u[(size_t)j*FDIM]; }
            }
            // mma on current buffer
            const uint32_t xb  = sb + SM_X  + cur*XBUF + arow;
            const uint32_t b0b = sb + SM_B0 + cur*BBUF + brow;
            const uint32_t b1b = sb + SM_B1 + cur*BBUF + brow;
            #pragma unroll
            for (int ks = 0; ks < 4; ks++) {
                uint32_t afr[2][4];
                #pragma unroll
                for (int ms = 0; ms < 2; ms++)
                    ldmx4(afr[ms], xb + ms*16*T_STRIDE + ks*32);
                #pragma unroll
                for (int j = 0; j < 2; j++) {
                    uint32_t bg[2], bu[2];
                    ldmx2(bg, b0b + j*8*T_STRIDE + ks*32);
                    ldmx2(bu, b1b + j*8*T_STRIDE + ks*32);
                    #pragma unroll
                    for (int ms = 0; ms < 2; ms++) {
                        mma16816(ag[ms][j], afr[ms], bg);
                        mma16816(au[ms][j], afr[ms], bu);
                    }
                }
            }
            if (more) {
                const int nb = cur ^ 1;
                *(uint4*)(smem + SM_X + nb*XBUF + xsts0) = pack8(pa0, pb0);
                *(uint4*)(smem + SM_X + nb*XBUF + xsts1) = pack8(pa1, pb1);
                *(uint4*)(smem + SM_B0 + nb*BBUF + wsts) = make_uint4(
                    pack_bf16x2(vg[0],vg[1]), pack_bf16x2(vg[2],vg[3]),
                    pack_bf16x2(vg[4],vg[5]), pack_bf16x2(vg[6],vg[7]));
                *(uint4*)(smem + SM_B1 + nb*BBUF + wsts) = make_uint4(
                    pack_bf16x2(vu[0],vu[1]), pack_bf16x2(vu[2],vu[3]),
                    pack_bf16x2(vu[4],vu[5]), pack_bf16x2(vu[6],vu[7]));
            }
            __syncthreads();
        }
        // epilogue: silu(g)*u -> H bf16
        #pragma unroll
        for (int ms = 0; ms < 2; ms++)
            #pragma unroll
            for (int j = 0; j < 2; j++)
                #pragma unroll
                for (int half = 0; half < 2; half++) {
                    int m   = mw*32 + ms*16 + quad + half*8;
                    int col = nc + nw*16 + j*8 + tq*2;
                    float g0 = ag[ms][j][half*2+0], g1 = ag[ms][j][half*2+1];
                    float u0 = au[ms][j][half*2+0], u1 = au[ms][j][half*2+1];
                    float h0 = g0 * u0 * __frcp_rn(1.f + __expf(-g0));
                    float h1 = g1 * u1 * __frcp_rn(1.f + __expf(-g1));
                    *(uint32_t*)(smem + SM_H + m*H_STRIDE + col*2) = pack_bf16x2(h0, h1);
                }
    }
    __syncthreads();

    // ================= stage 2: Y = (H * Wd) * w =================
    for (int nc2 = 0; nc2 < DIM; nc2 += 64) {
        float ac[2][2][4];
        #pragma unroll
        for (int i = 0; i < 2; i++)
            #pragma unroll
            for (int j = 0; j < 2; j++)
                #pragma unroll
                for (int q = 0; q < 4; q++) ac[i][j][q] = 0.f;

        const float* wdb = Wde + (size_t)wkg*8*DIM + nc2 + wn;

        // prologue
        {
            float v[8];
            #pragma unroll
            for (int j = 0; j < 8; j++) v[j] = wdb[(size_t)j*DIM];
            *(uint4*)(smem + SM_B0 + wsts) = make_uint4(
                pack_bf16x2(v[0],v[1]), pack_bf16x2(v[2],v[3]),
                pack_bf16x2(v[4],v[5]), pack_bf16x2(v[6],v[7]));
        }
        __syncthreads();

        for (int kci = 0; kci < 8; kci++) {
            const int cur = kci & 1;
            const bool more = (kci < 7);
            float v[8];
            if (more) {
                const float* d = wdb + (size_t)(kci + 1)*64*DIM;
                #pragma unroll
                for (int j = 0; j < 8; j++) v[j] = d[(size_t)j*DIM];
            }
            const int kc = kci*64;
            const uint32_t hb  = sb + SM_H + hrow + kc*2;
            const uint32_t b0b = sb + SM_B0 + cur*BBUF + brow;
            #pragma unroll
            for (int ks = 0; ks < 4; ks++) {
                uint32_t afr[2][4];
                #pragma unroll
                for (int ms = 0; ms < 2; ms++)
                    ldmx4(afr[ms], hb + ms*16*H_STRIDE + ks*32);
                #pragma unroll
                for (int j = 0; j < 2; j++) {
                    uint32_t bd[2];
                    ldmx2(bd, b0b + j*8*T_STRIDE + ks*32);
                    #pragma unroll
                    for (int ms = 0; ms < 2; ms++)
                        mma16816(ac[ms][j], afr[ms], bd);
                }
            }
            if (more) {
                const int nb = cur ^ 1;
                *(uint4*)(smem + SM_B0 + nb*BBUF + wsts) = make_uint4(
                    pack_bf16x2(v[0],v[1]), pack_bf16x2(v[2],v[3]),
                    pack_bf16x2(v[4],v[5]), pack_bf16x2(v[6],v[7]));
            }
            __syncthreads();
        }
        // epilogue
        #pragma unroll
        for (int ms = 0; ms < 2; ms++)
            #pragma unroll
            for (int half = 0; half < 2; half++) {
                int m = mw*32 + ms*16 + quad + half*8;
                if (m < M) {
                    float w = wro[m];
                    float* dst = Yout + (size_t)(base + m0 + m)*DIM + nc2;
                    #pragma unroll
                    for (int j = 0; j < 2; j++) {
                        int col = nw*16 + j*8 + tq*2;
                        *(float2*)(dst + col) = make_float2(ac[ms][j][half*2+0]*w,
                                                            ac[ms][j][half*2+1]*w);
                    }
                }
            }
    }
}

// ---------------- 4) combine ----------------
__global__ void combine_kernel(const float* __restrict__ x, float* __restrict__ out)
{
    __shared__ int sl[TOPK];
    const int b = blockIdx.x;
    const int t = b >> 1;
    const int d = ((b & 1) << 8) + threadIdx.x;
    if (threadIdx.x < TOPK) sl[threadIdx.x] = g_slot[t*TOPK + threadIdx.x];
    __syncthreads();

    const size_t o = (size_t)t*DIM + d;
    float v = x[o] + g_Ysh[o] + g_Ysh[(size_t)NTOK*DIM + o];
    #pragma unroll
    for (int k = 0; k < TOPK; k++) v += g_Yp[(size_t)sl[k]*DIM + d];
    out[o] = v;
}

// ---------------------------------- launch ---------------------------------------
extern "C" void kernel_launch(void* const* d_in, const int* in_sizes, int n_in,
                              void* d_out, int out_size)
{
    const float* x   = (const float*)d_in[0];
    const float* Wr  = (const float*)d_in[1];
    const float* sWg = (const float*)d_in[2];
    const float* sWu = (const float*)d_in[3];
    const float* sWd = (const float*)d_in[4];
    const float* Wg  = (const float*)d_in[5];
    const float* Wu  = (const float*)d_in[6];
    const float* Wd  = (const float*)d_in[7];
    float* out = (float*)d_out;

    cudaFuncSetAttribute(moe_ffn,      cudaFuncAttributeMaxDynamicSharedMemorySize, SMEM_BYTES);
    cudaFuncSetAttribute(build_kernel, cudaFuncAttributeMaxDynamicSharedMemorySize, NTOK*TOPK*4);

    router_kernel<<<NTOK, NEXP>>>(x, Wr);
    build_kernel<<<1, 256, NTOK*TOPK*4>>>();
    moe_ffn<<<dim3(NTOK/MT, NEXP + NSH), 512, SMEM_BYTES>>>(x, Wg, Wu, Wd, sWg, sWu, sWd);
    combine_kernel<<<NTOK*2, 256>>>(x, out);
}